// round 6
// baseline (speedup 1.0000x reference)
#include <cuda_runtime.h>
#include <cuda_bf16.h>
#include <cstdint>

#define DIM 128
#define NODES_MAX 50048
#define EDGES_MAX 800000

typedef __nv_bfloat16 bf16;
typedef __nv_bfloat162 bf162;

// ---------------- device scratch (allocation-free rule) ----------------
__device__ int   g_deg_i[NODES_MAX];
__device__ int   g_rowptr[NODES_MAX + 1];
__device__ int   g_csr[EDGES_MAX];
__device__ float g_invdeg[NODES_MAX];
__device__ __align__(16) float g_h[(size_t)NODES_MAX * DIM];   // fp32 activations (agg input)
__device__ __align__(16) float g_S[(size_t)NODES_MAX * DIM];   // self-GEMM partial (fp32)
__device__ __align__(16) bf16  g_xh[(size_t)NODES_MAX * DIM];  // split-bf16 GEMM inputs
__device__ __align__(16) bf16  g_xl[(size_t)NODES_MAX * DIM];
__device__ __align__(16) bf16  g_aggh[(size_t)NODES_MAX * DIM];
__device__ __align__(16) bf16  g_aggl[(size_t)NODES_MAX * DIM];
__device__ __align__(16) bf16  g_hh[(size_t)NODES_MAX * DIM];
__device__ __align__(16) bf16  g_hl[(size_t)NODES_MAX * DIM];
__device__ __align__(16) bf16  g_wth[6 * 16384];               // transposed [N][K] weight hi
__device__ __align__(16) bf16  g_wtl[6 * 16384];               // lo parts

// ---------------- PTX helpers (sm_80-baseline features only) ----------------
__device__ __forceinline__ uint32_t smem_to_u32(const void* p) {
    uint32_t a;
    asm("{ .reg .u64 t; cvta.to.shared.u64 t, %1; cvt.u32.u64 %0, t; }" : "=r"(a) : "l"(p));
    return a;
}
__device__ __forceinline__ void ldsm_x4(uint32_t* r, uint32_t addr) {
    asm volatile("ldmatrix.sync.aligned.m8n8.x4.shared.b16 {%0,%1,%2,%3}, [%4];"
                 : "=r"(r[0]), "=r"(r[1]), "=r"(r[2]), "=r"(r[3]) : "r"(addr));
}
__device__ __forceinline__ void mma_bf16(float* d, const uint32_t* a, const uint32_t* b) {
    asm volatile(
        "mma.sync.aligned.m16n8k16.row.col.f32.bf16.bf16.f32 "
        "{%0,%1,%2,%3}, {%4,%5,%6,%7}, {%8,%9}, {%0,%1,%2,%3};"
        : "+f"(d[0]), "+f"(d[1]), "+f"(d[2]), "+f"(d[3])
        : "r"(a[0]), "r"(a[1]), "r"(a[2]), "r"(a[3]), "r"(b[0]), "r"(b[1]));
}
__device__ __forceinline__ void cp16(uint32_t d, const void* g) {
    asm volatile("cp.async.cg.shared.global [%0], [%1], 16;" :: "r"(d), "l"(g));
}
__device__ __forceinline__ void zero16(uint32_t d) {
    asm volatile("st.shared.v4.b32 [%0], {%1,%1,%1,%1};" :: "r"(d), "r"(0u));
}
#define CP_COMMIT() asm volatile("cp.async.commit_group;" ::: "memory")
#define CP_WAIT1()  asm volatile("cp.async.wait_group 1;" ::: "memory")
#define CP_WAIT0()  asm volatile("cp.async.wait_group 0;" ::: "memory")

// ---------------- CSR build ----------------
__global__ void zero_int_kernel(int* __restrict__ p, int n) {
    int i = blockIdx.x * blockDim.x + threadIdx.x;
    if (i < n) p[i] = 0;
}
__global__ void deg_kernel(const int4* __restrict__ dst4, int* __restrict__ deg, int E4) {
    int e = blockIdx.x * blockDim.x + threadIdx.x;
    if (e < E4) {
        int4 d = __ldg(dst4 + e);
        atomicAdd(&deg[d.x], 1); atomicAdd(&deg[d.y], 1);
        atomicAdd(&deg[d.z], 1); atomicAdd(&deg[d.w], 1);
    }
}
// thread-coarsened single-block exclusive scan; also emits invdeg
__global__ void __launch_bounds__(1024)
scan_kernel(const int* __restrict__ cnt, int* __restrict__ rowptr,
            float* __restrict__ inv, int n) {
    __shared__ int wsum[32];
    const int tid = threadIdx.x;
    const int CH = (n + 1023) / 1024;
    const int base = tid * CH;
    int s = 0;
    for (int j = 0; j < CH; ++j) { int i = base + j; if (i < n) s += __ldg(cnt + i); }
    int v = s;
#pragma unroll
    for (int o = 1; o < 32; o <<= 1) { int u = __shfl_up_sync(~0u, v, o); if ((tid & 31) >= o) v += u; }
    if ((tid & 31) == 31) wsum[tid >> 5] = v;
    __syncthreads();
    if (tid < 32) {
        int w = wsum[tid];
#pragma unroll
        for (int o = 1; o < 32; o <<= 1) { int u = __shfl_up_sync(~0u, w, o); if (tid >= o) w += u; }
        wsum[tid] = w;
    }
    __syncthreads();
    int run = (v - s) + ((tid >= 32) ? wsum[(tid >> 5) - 1] : 0);
    for (int j = 0; j < CH; ++j) {
        int i = base + j;
        if (i < n) {
            int c = __ldg(cnt + i);
            run += c;
            rowptr[i + 1] = run;
            inv[i] = 1.0f / (float)max(c, 1);
        }
    }
    if (tid == 0) rowptr[0] = 0;
}
// fill via atomic countdown on deg (restores deg to all-zero for the next replay)
__global__ void fill_csr_kernel(const int4* __restrict__ src4, const int4* __restrict__ dst4,
                                const int* __restrict__ rowptr, int* __restrict__ deg,
                                int* __restrict__ csr, int E4) {
    int e = blockIdx.x * blockDim.x + threadIdx.x;
    if (e < E4) {
        int4 s = __ldg(src4 + e);
        int4 d = __ldg(dst4 + e);
        int c0 = atomicAdd(&deg[d.x], -1); csr[__ldg(rowptr + d.x) + c0 - 1] = s.x;
        int c1 = atomicAdd(&deg[d.y], -1); csr[__ldg(rowptr + d.y) + c1 - 1] = s.y;
        int c2 = atomicAdd(&deg[d.z], -1); csr[__ldg(rowptr + d.z) + c2 - 1] = s.z;
        int c3 = atomicAdd(&deg[d.w], -1); csr[__ldg(rowptr + d.w) + c3 - 1] = s.w;
    }
}

// ---------------- split conversions ----------------
__device__ __forceinline__ void split2(float v0, float v1, bf162& hi, bf162& lo) {
    bf16 h0 = __float2bfloat16(v0), h1 = __float2bfloat16(v1);
    bf16 l0 = __float2bfloat16(v0 - __bfloat162float(h0));
    bf16 l1 = __float2bfloat16(v1 - __bfloat162float(h1));
    hi = __halves2bfloat162(h0, h1);
    lo = __halves2bfloat162(l0, l1);
}
__global__ void split_kernel(const float* __restrict__ x, bf16* __restrict__ h,
                             bf16* __restrict__ l, int n2) {
    int i = blockIdx.x * blockDim.x + threadIdx.x;
    if (i < n2) {
        float2 v = reinterpret_cast<const float2*>(x)[i];
        bf162 hi, lo;
        split2(v.x, v.y, hi, lo);
        reinterpret_cast<bf162*>(h)[i] = hi;
        reinterpret_cast<bf162*>(l)[i] = lo;
    }
}
__global__ void wsplit_kernel(const float* W1s, const float* W1n, const float* W2s,
                              const float* W2n, const float* W3s, const float* W3n,
                              bf16* __restrict__ th, bf16* __restrict__ tl) {
    int i = blockIdx.x * blockDim.x + threadIdx.x;
    int m, off;
    if (i < 4 * 16384) { m = i / 16384; off = i % 16384; }
    else {
        int j = i - 4 * 16384;
        if (j >= 2 * 8192) return;
        m = 4 + j / 8192; off = j % 8192;
    }
    const float* src = (m == 0) ? W1s : (m == 1) ? W1n : (m == 2) ? W2s
                     : (m == 3) ? W2n : (m == 4) ? W3s : W3n;
    int Ncols = (m < 4) ? 128 : 64;
    int nn = off / 128, kk = off % 128;
    float v = src[kk * Ncols + nn];
    bf16 h = __float2bfloat16(v);
    th[m * 16384 + off] = h;
    tl[m * 16384 + off] = __float2bfloat16(v - __bfloat162float(h));
}

// ---------------- atomic-free mean aggregation (fp32 gather -> split bf16 out) ----------------
__global__ void __launch_bounds__(256)
agg_kernel(const float* __restrict__ feat, const int* __restrict__ rowptr,
           const int* __restrict__ csr, const float* __restrict__ invdeg,
           bf16* __restrict__ aggh, bf16* __restrict__ aggl, int n) {
    long long t = (long long)blockIdx.x * blockDim.x + threadIdx.x;
    int v = (int)(t >> 5);
    if (v >= n) return;
    int lane = (int)(t & 31);

    int beg = __ldg(rowptr + v);
    int end = __ldg(rowptr + v + 1);

    float ax = 0.f, ay = 0.f, az = 0.f, aw = 0.f;
    int i = beg;
    for (; i + 4 <= end; i += 4) {
        int s0 = __ldg(csr + i + 0);
        int s1 = __ldg(csr + i + 1);
        int s2 = __ldg(csr + i + 2);
        int s3 = __ldg(csr + i + 3);
        float4 f0 = *reinterpret_cast<const float4*>(feat + (size_t)s0 * DIM + lane * 4);
        float4 f1 = *reinterpret_cast<const float4*>(feat + (size_t)s1 * DIM + lane * 4);
        float4 f2 = *reinterpret_cast<const float4*>(feat + (size_t)s2 * DIM + lane * 4);
        float4 f3 = *reinterpret_cast<const float4*>(feat + (size_t)s3 * DIM + lane * 4);
        ax += (f0.x + f1.x) + (f2.x + f3.x);
        ay += (f0.y + f1.y) + (f2.y + f3.y);
        az += (f0.z + f1.z) + (f2.z + f3.z);
        aw += (f0.w + f1.w) + (f2.w + f3.w);
    }
    for (; i < end; ++i) {
        int s0 = __ldg(csr + i);
        float4 f0 = *reinterpret_cast<const float4*>(feat + (size_t)s0 * DIM + lane * 4);
        ax += f0.x; ay += f0.y; az += f0.z; aw += f0.w;
    }
    float sc = __ldg(invdeg + v);
    bf162 h01, l01, h23, l23;
    split2(ax * sc, ay * sc, h01, l01);
    split2(az * sc, aw * sc, h23, l23);
    reinterpret_cast<bf162*>(aggh + (size_t)v * DIM)[lane * 2 + 0] = h01;
    reinterpret_cast<bf162*>(aggh + (size_t)v * DIM)[lane * 2 + 1] = h23;
    reinterpret_cast<bf162*>(aggl + (size_t)v * DIM)[lane * 2 + 0] = l01;
    reinterpret_cast<bf162*>(aggl + (size_t)v * DIM)[lane * 2 + 1] = l23;
}

// ---------------- HMMA half-layer GEMM: persistent, cp.async double-buffered ----------------
// smem: [stage0: 2 x 8KB act tiles][stage1] @0/16384; weights @32768 (2 x NOUT*256B).
__device__ __forceinline__ void load_swz(const bf16* __restrict__ g, char* __restrict__ s,
                                         int rows, int t) {
    for (int i = t; i < rows * 16; i += 256) {
        int row = i >> 4, c = i & 15;
        uint4 v = *reinterpret_cast<const uint4*>(g + (size_t)row * 128 + c * 8);
        *reinterpret_cast<uint4*>(s + (size_t)row * 256 + ((c ^ (row & 7)) << 4)) = v;
    }
}
__device__ __forceinline__ void issue2(const bf16* __restrict__ a, const bf16* __restrict__ b,
                                       int row0, int n, uint32_t stage, int t) {
    int valid = min(32, n - row0);
    for (int i = t; i < 512; i += 256) {
        int row = i >> 4, c = i & 15;
        uint32_t off = (uint32_t)row * 256u + (uint32_t)((c ^ (row & 7)) << 4);
        size_t goff = (size_t)(row0 + row) * 128 + c * 8;
        if (row < valid) {
            cp16(stage + off,         a + goff);
            cp16(stage + 8192u + off, b + goff);
        } else {
            zero16(stage + off);
            zero16(stage + 8192u + off);
        }
    }
}

// MODE 0: S = A@W + bias (aux=bias)            -> outf
// MODE 1: h = relu(S + A@W); also bf16 split   (aux=S) -> outf, oh, ol
// MODE 2: out = S + A@W                        (aux=S) -> outf
template <int NOUT, int MODE>
__global__ void __launch_bounds__(256, 1)
gemm_kernel(const bf16* __restrict__ ah, const bf16* __restrict__ al,
            const bf16* __restrict__ wh, const bf16* __restrict__ wl,
            const float* __restrict__ aux, float* __restrict__ outf,
            bf16* __restrict__ oh, bf16* __restrict__ ol, int n, int ntiles) {
    extern __shared__ char smem[];
    constexpr int NB = NOUT * 256;
    constexpr int WBASE = 32768;
    constexpr int NPW = NOUT / 4;
    constexpr int NT = NPW / 8;
    const uint32_t sb = smem_to_u32(smem);
    const uint32_t wb = sb + WBASE;
    const int t = threadIdx.x, lane = t & 31, wid = t >> 5;

    load_swz(wh, smem + WBASE,      NOUT, t);
    load_swz(wl, smem + WBASE + NB, NOUT, t);

    const int rhalf = (wid & 1) * 16;
    const int n0 = (wid >> 1) * NPW;
    const int arowl = rhalf + (lane & 15);
    const int akh = lane >> 4;
    const int browl = ((lane >> 4) << 3) + (lane & 7);
    const int bkh = (lane >> 3) & 1;

    float breg[NT][2];
    if (MODE == 0) {
#pragma unroll
        for (int nt = 0; nt < NT; ++nt) {
            int c = n0 + nt * 8 + (lane & 3) * 2;
            breg[nt][0] = __ldg(aux + c);
            breg[nt][1] = __ldg(aux + c + 1);
        }
    }

    int tile = blockIdx.x, buf = 0;
    issue2(ah, al, tile * 32, n, sb, t);
    CP_COMMIT();

    for (; tile < ntiles; tile += gridDim.x) {
        const int nxt = tile + gridDim.x;
        if (nxt < ntiles) {
            issue2(ah, al, nxt * 32, n, sb + (uint32_t)(buf ^ 1) * 16384u, t);
            CP_COMMIT();
            CP_WAIT1();
        } else {
            CP_WAIT0();
        }
        __syncthreads();

        const uint32_t ab = sb + (uint32_t)buf * 16384u;
        float acc[NT][4];
#pragma unroll
        for (int q = 0; q < NT; ++q) { acc[q][0] = acc[q][1] = acc[q][2] = acc[q][3] = 0.f; }

#pragma unroll
        for (int ks = 0; ks < 8; ++ks) {
            uint32_t ac = (uint32_t)((2 * ks + akh) ^ (arowl & 7));
            uint32_t aoff = (uint32_t)arowl * 256u + (ac << 4);
            uint32_t Ah[4], Al[4];
            ldsm_x4(Ah, ab + aoff);
            ldsm_x4(Al, ab + 8192u + aoff);
#pragma unroll
            for (int np = 0; np < NT / 2; ++np) {
                int brow = n0 + np * 16 + browl;
                uint32_t bc = (uint32_t)((2 * ks + bkh) ^ (brow & 7));
                uint32_t boff = (uint32_t)brow * 256u + (bc << 4);
                uint32_t Bh[4], Bl[4];
                ldsm_x4(Bh, wb + boff);
                ldsm_x4(Bl, wb + (uint32_t)NB + boff);
                float* a0 = acc[np * 2];
                float* a1 = acc[np * 2 + 1];
                mma_bf16(a0, Ah, Bh);  mma_bf16(a1, Ah, Bh + 2);
                mma_bf16(a0, Al, Bh);  mma_bf16(a1, Al, Bh + 2);
                mma_bf16(a0, Ah, Bl);  mma_bf16(a1, Ah, Bl + 2);
            }
        }

        const int r0 = tile * 32 + rhalf + (lane >> 2);
        const int r1 = r0 + 8;
#pragma unroll
        for (int nt = 0; nt < NT; ++nt) {
            int c = n0 + nt * 8 + (lane & 3) * 2;
            float v0 = acc[nt][0], v1 = acc[nt][1], v2 = acc[nt][2], v3 = acc[nt][3];
            if (MODE == 0) {
                v0 += breg[nt][0]; v1 += breg[nt][1];
                v2 += breg[nt][0]; v3 += breg[nt][1];
            }
            if (r0 < n) {
                if (MODE != 0) {
                    float2 s = *reinterpret_cast<const float2*>(aux + (size_t)r0 * NOUT + c);
                    v0 += s.x; v1 += s.y;
                    if (MODE == 1) { v0 = fmaxf(v0, 0.f); v1 = fmaxf(v1, 0.f); }
                }
                *reinterpret_cast<float2*>(outf + (size_t)r0 * NOUT + c) = make_float2(v0, v1);
                if (MODE == 1) {
                    bf162 hi, lo;
                    split2(v0, v1, hi, lo);
                    *reinterpret_cast<bf162*>(oh + (size_t)r0 * NOUT + c) = hi;
                    *reinterpret_cast<bf162*>(ol + (size_t)r0 * NOUT + c) = lo;
                }
            }
            if (r1 < n) {
                if (MODE != 0) {
                    float2 s = *reinterpret_cast<const float2*>(aux + (size_t)r1 * NOUT + c);
                    v2 += s.x; v3 += s.y;
                    if (MODE == 1) { v2 = fmaxf(v2, 0.f); v3 = fmaxf(v3, 0.f); }
                }
                *reinterpret_cast<float2*>(outf + (size_t)r1 * NOUT + c) = make_float2(v2, v3);
                if (MODE == 1) {
                    bf162 hi, lo;
                    split2(v2, v3, hi, lo);
                    *reinterpret_cast<bf162*>(oh + (size_t)r1 * NOUT + c) = hi;
                    *reinterpret_cast<bf162*>(ol + (size_t)r1 * NOUT + c) = lo;
                }
            }
        }
        __syncthreads();
        buf ^= 1;
    }
}

// ---------------- launch ----------------
extern "C" void kernel_launch(void* const* d_in, const int* in_sizes, int n_in,
                              void* d_out, int out_size) {
    const float* x   = (const float*)d_in[0];
    const int*   src = (const int*)d_in[1];
    const int*   dst = (const int*)d_in[2];
    const float* Ws1 = (const float*)d_in[3];
    const float* b1  = (const float*)d_in[4];
    const float* Wn1 = (const float*)d_in[5];
    const float* Ws2 = (const float*)d_in[6];
    const float* b2  = (const float*)d_in[7];
    const float* Wn2 = (const float*)d_in[8];
    const float* Ws3 = (const float*)d_in[9];
    const float* b3  = (const float*)d_in[10];
    const float* Wn3 = (const float*)d_in[11];

    const int N = in_sizes[0] / DIM;
    const int E = in_sizes[1];
    float* out = (float*)d_out;

    int *deg_i, *rowptr, *csr;
    float *invdeg, *h, *S;
    bf16 *xh, *xl, *aggh, *aggl, *hh, *hl, *wth, *wtl;
    cudaGetSymbolAddress((void**)&deg_i,  g_deg_i);
    cudaGetSymbolAddress((void**)&rowptr, g_rowptr);
    cudaGetSymbolAddress((void**)&csr,    g_csr);
    cudaGetSymbolAddress((void**)&invdeg, g_invdeg);
    cudaGetSymbolAddress((void**)&h,      g_h);
    cudaGetSymbolAddress((void**)&S,      g_S);
    cudaGetSymbolAddress((void**)&xh,     g_xh);
    cudaGetSymbolAddress((void**)&xl,     g_xl);
    cudaGetSymbolAddress((void**)&aggh,   g_aggh);
    cudaGetSymbolAddress((void**)&aggl,   g_aggl);
    cudaGetSymbolAddress((void**)&hh,     g_hh);
    cudaGetSymbolAddress((void**)&hl,     g_hl);
    cudaGetSymbolAddress((void**)&wth,    g_wth);
    cudaGetSymbolAddress((void**)&wtl,    g_wtl);

    // one-time host-side setup (runs on the non-captured correctness call first)
    static cudaStream_t s1 = nullptr;
    static cudaEvent_t evf, ea1, eh1, ea2, eh2, ea3;
    if (!s1) {
        cudaStreamCreateWithFlags(&s1, cudaStreamNonBlocking);
        cudaEventCreateWithFlags(&evf, cudaEventDisableTiming);
        cudaEventCreateWithFlags(&ea1, cudaEventDisableTiming);
        cudaEventCreateWithFlags(&eh1, cudaEventDisableTiming);
        cudaEventCreateWithFlags(&ea2, cudaEventDisableTiming);
        cudaEventCreateWithFlags(&eh2, cudaEventDisableTiming);
        cudaEventCreateWithFlags(&ea3, cudaEventDisableTiming);
        const int SM128 = 32768 + 2 * 128 * 256;  // 98304
        const int SM64  = 32768 + 2 * 64 * 256;   // 65536
        cudaFuncSetAttribute(gemm_kernel<128, 0>, cudaFuncAttributeMaxDynamicSharedMemorySize, SM128);
        cudaFuncSetAttribute(gemm_kernel<128, 1>, cudaFuncAttributeMaxDynamicSharedMemorySize, SM128);
        cudaFuncSetAttribute(gemm_kernel<64, 0>,  cudaFuncAttributeMaxDynamicSharedMemorySize, SM64);
        cudaFuncSetAttribute(gemm_kernel<64, 2>,  cudaFuncAttributeMaxDynamicSharedMemorySize, SM64);
    }
    const int SM128 = 32768 + 2 * 128 * 256;
    const int SM64  = 32768 + 2 * 64 * 256;

    const int nb_nodes = (N + 255) / 256;
    const int nb_edges4 = (E / 4 + 255) / 256;
    const int nb_agg   = (int)(((long long)N * 32 + 255) / 256);
    const int ntiles   = (N + 31) / 32;
    const int GRID     = 152;

    // ---- fork: s1 handles CSR build + aggregations ----
    cudaEventRecord(evf, 0);
    cudaStreamWaitEvent(s1, evf, 0);

    // s1: CSR build + agg1 (reads fp32 x directly)
    zero_int_kernel<<<nb_nodes, 256, 0, s1>>>(deg_i, N);
    deg_kernel<<<nb_edges4, 256, 0, s1>>>((const int4*)dst, deg_i, E / 4);
    scan_kernel<<<1, 1024, 0, s1>>>(deg_i, rowptr, invdeg, N);
    fill_csr_kernel<<<nb_edges4, 256, 0, s1>>>((const int4*)src, (const int4*)dst,
                                               rowptr, deg_i, csr, E / 4);
    agg_kernel<<<nb_agg, 256, 0, s1>>>(x, rowptr, csr, invdeg, aggh, aggl, N);
    cudaEventRecord(ea1, s1);

    // s0 (capture stream): splits + self-GEMM layer 1 (independent of CSR)
    split_kernel<<<(N * DIM / 2 + 255) / 256, 256>>>(x, xh, xl, N * DIM / 2);
    wsplit_kernel<<<(81920 + 255) / 256, 256>>>(Ws1, Wn1, Ws2, Wn2, Ws3, Wn3, wth, wtl);
    gemm_kernel<128, 0><<<GRID, 256, SM128>>>(
        xh, xl, wth + 0 * 16384, wtl + 0 * 16384, b1, S, nullptr, nullptr, N, ntiles);

    // join: layer-1 neigh GEMM -> h
    cudaStreamWaitEvent(0, ea1, 0);
    gemm_kernel<128, 1><<<GRID, 256, SM128>>>(
        aggh, aggl, wth + 1 * 16384, wtl + 1 * 16384, S, h, hh, hl, N, ntiles);
    cudaEventRecord(eh1, 0);

    // layer 2: agg2 (s1) || self2 (s0)
    cudaStreamWaitEvent(s1, eh1, 0);
    agg_kernel<<<nb_agg, 256, 0, s1>>>(h, rowptr, csr, invdeg, aggh, aggl, N);
    cudaEventRecord(ea2, s1);
    gemm_kernel<128, 0><<<GRID, 256, SM128>>>(
        hh, hl, wth + 2 * 16384, wtl + 2 * 16384, b2, S, nullptr, nullptr, N, ntiles);
    cudaStreamWaitEvent(0, ea2, 0);
    gemm_kernel<128, 1><<<GRID, 256, SM128>>>(
        aggh, aggl, wth + 3 * 16384, wtl + 3 * 16384, S, h, hh, hl, N, ntiles);
    cudaEventRecord(eh2, 0);

    // layer 3: agg3 (s1) || self3 (s0); final neigh writes d_out
    cudaStreamWaitEvent(s1, eh2, 0);
    agg_kernel<<<nb_agg, 256, 0, s1>>>(h, rowptr, csr, invdeg, aggh, aggl, N);
    cudaEventRecord(ea3, s1);
    gemm_kernel<64, 0><<<GRID, 256, SM64>>>(
        hh, hl, wth + 4 * 16384, wtl + 4 * 16384, b3, S, nullptr, nullptr, N, ntiles);
    cudaStreamWaitEvent(0, ea3, 0);
    gemm_kernel<64, 2><<<GRID, 256, SM64>>>(
        aggh, aggl, wth + 5 * 16384, wtl + 5 * 16384, S, out, nullptr, nullptr, N, ntiles);
}